// round 16
// baseline (speedup 1.0000x reference)
#include <cuda_runtime.h>
#include <cuda_bf16.h>
#include <mma.h>
#include <math.h>

using namespace nvcuda;

#define NN 6000
#define EE 100000

// ---------------- scratch (device-only; NEVER passed from host) ----------------
__device__ float g_x[NN * 64];          // ping
__device__ float g_y[NN * 64];          // pong
__device__ float g_hr[2 * NN * 32];     // layer0 relation rows
__device__ float g_W1[32 * 128];        // [I, 2*O]
__device__ float g_W2[64 * 128];
__device__ float g_W3[64 * 64];
__device__ int   g_cnt[2 * NN];
__device__ float g_rinv[2 * NN];
__device__ int   g_offs[NN + 1];
__device__ int   g_cur[NN];
__device__ int   g_csr[EE];             // src | (rel<<16)
__device__ __align__(16) __nv_bfloat16 g_h[NN * 512];   // bf16 GAT features
__device__ float g_asv[NN], g_adv[NN];
__device__ float g_o512[NN * 512];      // holds relu(gat_out + gbias)
__device__ __align__(16) __nv_bfloat16 g_A[NN * 128];   // bf16 edge-MLP halves
__device__ __align__(16) __nv_bfloat16 g_B[NN * 128];

__device__ __forceinline__ unsigned pkbf(float a, float b) {
    __nv_bfloat162 t = __floats2bfloat162_rn(a, b);
    return *(unsigned*)&t;
}
__device__ __forceinline__ float2 upbf(unsigned u) {
    return __bfloat1622float2(*(__nv_bfloat162*)&u);
}

// ---------------- fused init: zero counters + all weight precomputes ----------------
__device__ __forceinline__ void wcat_one(float* W, const float* basis, const float* comp,
                                         int I, int O, int i) {
    int r = i / (I * O), io = i % (I * O);
    float acc = 0.f;
#pragma unroll
    for (int b = 0; b < 4; b++) acc += comp[r * 4 + b] * basis[b * I * O + io];
    W[(io / O) * 2 * O + r * O + (io % O)] = acc;
}
#define R0 (2 * NN * 32)
__global__ void init_k(const float* __restrict__ basis0, const float* __restrict__ comp0,
                       const float* __restrict__ b1s, const float* __restrict__ c1,
                       const float* __restrict__ b2s, const float* __restrict__ c2,
                       const float* __restrict__ b3s, const float* __restrict__ c3) {
    int i = blockIdx.x * blockDim.x + threadIdx.x;
    if (i < 2 * NN) g_cnt[i] = 0;
    if (i < NN) { g_cur[i] = 0; g_asv[i] = 0.f; g_adv[i] = 0.f; }
    if (i < R0) {
        int r = i / (NN * 32), idx = i % (NN * 32);
        float acc = 0.f;
#pragma unroll
        for (int b = 0; b < 4; b++) acc += comp0[r * 4 + b] * basis0[b * NN * 32 + idx];
        g_hr[r * NN * 32 + idx] = acc;
    } else if (i < R0 + 4096) {
        wcat_one(g_W1, b1s, c1, 32, 64, i - R0);
    } else if (i < R0 + 4096 + 8192) {
        wcat_one(g_W2, b2s, c2, 64, 64, i - R0 - 4096);
    } else if (i < R0 + 4096 + 8192 + 4096) {
        wcat_one(g_W3, b3s, c3, 64, 32, i - R0 - 4096 - 8192);
    }
}

__global__ void count_k(const int* __restrict__ et, const int* __restrict__ dst) {
    int e = blockIdx.x * blockDim.x + threadIdx.x;
    if (e < EE) atomicAdd(&g_cnt[et[e] * NN + dst[e]], 1);
}
// scan of deg (=cnt0+cnt1) + rinv, single block 1024 threads
__global__ void scan_k() {
    __shared__ int ws[32];
    int t = threadIdx.x;
    for (int i = t; i < 2 * NN; i += 1024)
        g_rinv[i] = 1.0f / fmaxf((float)g_cnt[i], 1.0f);
    int base = t * 6;
    int loc[6]; int s = 0;
#pragma unroll
    for (int j = 0; j < 6; j++) {
        int idx = base + j; loc[j] = s;
        s += (idx < NN) ? (g_cnt[idx] + g_cnt[NN + idx]) : 0;
    }
    int lane = t & 31, w = t >> 5;
    int v = s;
#pragma unroll
    for (int off = 1; off < 32; off <<= 1) {
        int nv = __shfl_up_sync(0xffffffffu, v, off);
        if (lane >= off) v += nv;
    }
    if (lane == 31) ws[w] = v;
    __syncthreads();
    if (w == 0) {
        int x = ws[lane];
#pragma unroll
        for (int off = 1; off < 32; off <<= 1) {
            int nv = __shfl_up_sync(0xffffffffu, x, off);
            if (lane >= off) x += nv;
        }
        ws[lane] = x;
    }
    __syncthreads();
    int excl = v - s + (w ? ws[w - 1] : 0);
#pragma unroll
    for (int j = 0; j < 6; j++) {
        int idx = base + j;
        if (idx < NN) g_offs[idx] = excl + loc[j];
    }
    if (t == 1023) g_offs[NN] = excl + s;
}
__global__ void scatter_k(const int* __restrict__ src, const int* __restrict__ dst,
                          const int* __restrict__ et) {
    int e = blockIdx.x * blockDim.x + threadIdx.x;
    if (e >= EE) return;
    int d = dst[e];
    int pos = g_offs[d] + atomicAdd(&g_cur[d], 1);
    g_csr[pos] = src[e] | (et[e] << 16);
}

// ---------------- layer 0: gather + root + bias + tanh ----------------
__global__ void l0_agg_k(const float* __restrict__ root0, const float* __restrict__ rbias0) {
    int n = blockIdx.x * 4 + (threadIdx.x >> 5);
    int lane = threadIdx.x & 31;
    if (n >= NN) return;
    int o = g_offs[n], e2 = g_offs[n + 1];
    float a0 = 0.f, a1 = 0.f;
    for (int p = o; p < e2; p++) {
        int pk = g_csr[p];
        float v = g_hr[(pk >> 16) * NN * 32 + (pk & 0xffff) * 32 + lane];
        if (pk & 0x10000) a1 += v; else a0 += v;
    }
    float out = root0[n * 32 + lane] + rbias0[lane] + a0 * g_rinv[n] + a1 * g_rinv[NN + n];
    g_x[n * 32 + lane] = tanhf(out);
}

// ---------------- fused RGCN layer: aggregate + GEMM + tanh ----------------
__global__ void layer_k(const float* __restrict__ root, const float* __restrict__ rbias,
                        int layer, int I, int O, int inflag) {
    __shared__ float xs[4][64], a0s[4][64], a1s[4][64];
    const float* xin = inflag ? g_y : g_x;
    float* xout = inflag ? g_x : g_y;
    const float* Wcat = (layer == 1) ? g_W1 : (layer == 2) ? g_W2 : g_W3;
    int ty = threadIdx.y, tx = threadIdx.x;
    int n = blockIdx.x * 4 + ty;
    if (tx < I) {
        int o = g_offs[n], e2 = g_offs[n + 1];
        float a0 = 0.f, a1 = 0.f;
#pragma unroll 4
        for (int p = o; p < e2; p++) {
            int pk = g_csr[p];
            float v = xin[(pk & 0xffff) * I + tx];
            if (pk & 0x10000) a1 += v; else a0 += v;
        }
        xs[ty][tx] = xin[n * I + tx];
        a0s[ty][tx] = a0 * g_rinv[n];
        a1s[ty][tx] = a1 * g_rinv[NN + n];
    }
    __syncthreads();
    if (tx < O) {
        float acc = rbias[tx];
#pragma unroll 8
        for (int i = 0; i < I; i++) {
            acc += xs[ty][i] * root[i * O + tx];
            acc += a0s[ty][i] * Wcat[i * 2 * O + tx];
            acc += a1s[ty][i] * Wcat[i * 2 * O + O + tx];
        }
        xout[n * O + tx] = tanhf(acc);
    }
}

// ---------------- GAT h GEMM + fused attention partials (h stored bf16) ----------------
__global__ void gath_gemm_k(const float* __restrict__ gw, const float* __restrict__ asrc,
                            const float* __restrict__ adst) {
    __shared__ float As[32][68];
    __shared__ float Bs[32][128];
    int tid = threadIdx.x;
    int bm = blockIdx.x * 64, bn = blockIdx.y * 128;
    int ty = tid >> 4, tx = tid & 15;
    {
        int mm = tid & 63, kg = tid >> 6;
#pragma unroll
        for (int r = 0; r < 2; r++) {
            int k = kg * 8 + r * 4;
            int gm = bm + mm;
            float4 v = make_float4(0.f, 0.f, 0.f, 0.f);
            if (gm < NN) v = *(const float4*)&g_y[gm * 32 + k];
            As[k + 0][mm] = v.x; As[k + 1][mm] = v.y;
            As[k + 2][mm] = v.z; As[k + 3][mm] = v.w;
        }
    }
    {
        int id = tid * 4;
#pragma unroll
        for (int rep = 0; rep < 4; rep++, id += 1024) {
            int kk = id >> 7, col = id & 127;
            *(float4*)&Bs[kk][col] = *(const float4*)&gw[kk * 512 + bn + col];
        }
    }
    __syncthreads();
    float acc[4][8] = {};
#pragma unroll
    for (int kk = 0; kk < 32; kk++) {
        float a[4], bb[8];
#pragma unroll
        for (int i = 0; i < 4; i++) a[i] = As[kk][ty * 4 + i];
#pragma unroll
        for (int j = 0; j < 8; j++) bb[j] = Bs[kk][tx * 8 + j];
#pragma unroll
        for (int i = 0; i < 4; i++)
#pragma unroll
            for (int j = 0; j < 8; j++) acc[i][j] += a[i] * bb[j];
    }
    // store h tile as bf16 (8 values = one uint4 per row-slice)
#pragma unroll
    for (int i = 0; i < 4; i++) {
        int gm = bm + ty * 4 + i;
        if (gm >= NN) continue;
        uint4 pk;
        pk.x = pkbf(acc[i][0], acc[i][1]);
        pk.y = pkbf(acc[i][2], acc[i][3]);
        pk.z = pkbf(acc[i][4], acc[i][5]);
        pk.w = pkbf(acc[i][6], acc[i][7]);
        *(uint4*)&g_h[gm * 512 + bn + tx * 8] = pk;
    }
    // fused attention partials (fp32-exact, computed before rounding)
    float sa[8], da[8];
#pragma unroll
    for (int j = 0; j < 8; j++) {
        sa[j] = asrc[bn + tx * 8 + j];
        da[j] = adst[bn + tx * 8 + j];
    }
#pragma unroll
    for (int i = 0; i < 4; i++) {
        float pa = 0.f, pd = 0.f;
#pragma unroll
        for (int j = 0; j < 8; j++) { pa += acc[i][j] * sa[j]; pd += acc[i][j] * da[j]; }
#pragma unroll
        for (int off = 8; off; off >>= 1) {
            pa += __shfl_down_sync(0xffffffffu, pa, off, 16);
            pd += __shfl_down_sync(0xffffffffu, pd, off, 16);
        }
        int gm = bm + ty * 4 + i;
        if (tx == 0 && gm < NN) {
            atomicAdd(&g_asv[gm], pa);
            atomicAdd(&g_adv[gm], pd);
        }
    }
}

// ---------------- GAT softmax + weighted sum (bf16 gathers) + fused gbias/relu ----------------
__global__ void gat_node_k(const float* __restrict__ gbias) {
    __shared__ float sal[4][512];
    __shared__ int ssrc[4][512];
    int wid = threadIdx.x >> 5, lane = threadIdx.x & 31;
    int n = blockIdx.x * 4 + wid;
    if (n >= NN) return;
    int o = g_offs[n];
    int deg = g_offs[n + 1] - o;
    if (deg > 512) deg = 512;
    float advn = g_adv[n];
    float* wsal = sal[wid];
    int* wsrc = ssrc[wid];
    float lm = -1e30f;
    for (int p = lane; p < deg; p += 32) {
        int s = g_csr[o + p] & 0xffff;
        wsrc[p] = s;
        float a = g_asv[s] + advn;
        a = a > 0.f ? a : 0.2f * a;
        wsal[p] = a;
        lm = fmaxf(lm, a);
    }
    float als = g_asv[n] + advn;
    als = als > 0.f ? als : 0.2f * als;
    lm = fmaxf(lm, als);
#pragma unroll
    for (int off = 16; off; off >>= 1)
        lm = fmaxf(lm, __shfl_xor_sync(0xffffffffu, lm, off));
    float m = lm;
    float ls = 0.f;
    __syncwarp();
    for (int p = lane; p < deg; p += 32) {
        float ex = expf(wsal[p] - m);
        wsal[p] = ex;
        ls += ex;
    }
    float exs = expf(als - m);
    if (lane == 0) ls += exs;
#pragma unroll
    for (int off = 16; off; off >>= 1)
        ls += __shfl_xor_sync(0xffffffffu, ls, off);
    float invden = 1.f / fmaxf(ls, 1e-16f);
    float cs = exs * invden;
    __syncwarp();
#pragma unroll
    for (int q = 0; q < 4; q++) {
        int cidx = q * 32 + lane;
        uint2 hu = *(const uint2*)&g_h[n * 512 + cidx * 4];
        float2 hlo = upbf(hu.x), hhi = upbf(hu.y);
        float4 acc;
        acc.x = cs * hlo.x; acc.y = cs * hlo.y; acc.z = cs * hhi.x; acc.w = cs * hhi.y;
        for (int p = 0; p < deg; p++) {
            int s = wsrc[p];
            float c = wsal[p] * invden;
            uint2 u = *(const uint2*)&g_h[s * 512 + cidx * 4];
            float2 lo = upbf(u.x), hi = upbf(u.y);
            acc.x += c * lo.x; acc.y += c * lo.y; acc.z += c * hi.x; acc.w += c * hi.y;
        }
        float4 gb = ((const float4*)gbias)[cidx];
        acc.x = fmaxf(acc.x + gb.x, 0.f);
        acc.y = fmaxf(acc.y + gb.y, 0.f);
        acc.z = fmaxf(acc.z + gb.z, 0.f);
        acc.w = fmaxf(acc.w + gb.w, 0.f);
        ((float4*)&g_o512[n * 512])[cidx] = acc;
    }
}

// ---------------- AB GEMM on tensor cores (wmma tf32), bf16 output ----------------
__global__ void ab_gemm_k(const float* __restrict__ w1, const float* __restrict__ b1) {
    __shared__ __align__(16) float sbuf[8192];
    float (*As)[32]  = (float(*)[32])sbuf;           // [64][32]
    float (*Bs)[128] = (float(*)[128])(sbuf + 2048); // [32][128]
    float (*Os)[128] = (float(*)[128])sbuf;          // [64][128] epilogue

    int tid = threadIdx.x;                 // 256
    int wid = tid >> 5;
    int warpRow = wid >> 2;
    int warpCol = wid & 3;
    int bm = blockIdx.x * 64;
    int by = blockIdx.y;

    wmma::fragment<wmma::accumulator, 16, 16, 8, float> c[2][2];
#pragma unroll
    for (int i = 0; i < 2; i++)
#pragma unroll
        for (int j = 0; j < 2; j++) wmma::fill_fragment(c[i][j], 0.f);

    for (int k0 = 0; k0 < 512; k0 += 32) {
        {
            int mm = tid & 63, kg = tid >> 6;
            int gm = bm + mm;
#pragma unroll
            for (int r = 0; r < 2; r++) {
                int k = kg * 8 + r * 4;
                float4 v = make_float4(0.f, 0.f, 0.f, 0.f);
                if (gm < NN) v = *(const float4*)&g_o512[gm * 512 + k0 + k];
                As[mm][k + 0] = wmma::__float_to_tf32(v.x);
                As[mm][k + 1] = wmma::__float_to_tf32(v.y);
                As[mm][k + 2] = wmma::__float_to_tf32(v.z);
                As[mm][k + 3] = wmma::__float_to_tf32(v.w);
            }
        }
        {
            int id = tid * 4;
#pragma unroll
            for (int rep = 0; rep < 4; rep++, id += 1024) {
                int kk = id >> 7, col = id & 127;
                float4 v = *(const float4*)&w1[(k0 + kk + by * 512) * 128 + col];
                Bs[kk][col + 0] = wmma::__float_to_tf32(v.x);
                Bs[kk][col + 1] = wmma::__float_to_tf32(v.y);
                Bs[kk][col + 2] = wmma::__float_to_tf32(v.z);
                Bs[kk][col + 3] = wmma::__float_to_tf32(v.w);
            }
        }
        __syncthreads();
#pragma unroll
        for (int ks = 0; ks < 4; ks++) {
            wmma::fragment<wmma::matrix_a, 16, 16, 8, wmma::precision::tf32, wmma::row_major> a[2];
            wmma::fragment<wmma::matrix_b, 16, 16, 8, wmma::precision::tf32, wmma::row_major> bf[2];
#pragma unroll
            for (int i = 0; i < 2; i++)
                wmma::load_matrix_sync(a[i], &As[warpRow * 32 + i * 16][ks * 8], 32);
#pragma unroll
            for (int j = 0; j < 2; j++)
                wmma::load_matrix_sync(bf[j], &Bs[ks * 8][warpCol * 32 + j * 16], 128);
#pragma unroll
            for (int i = 0; i < 2; i++)
#pragma unroll
                for (int j = 0; j < 2; j++)
                    wmma::mma_sync(c[i][j], a[i], bf[j], c[i][j]);
        }
        __syncthreads();
    }
#pragma unroll
    for (int i = 0; i < 2; i++)
#pragma unroll
        for (int j = 0; j < 2; j++)
            wmma::store_matrix_sync(&Os[warpRow * 32 + i * 16][warpCol * 32 + j * 16],
                                    c[i][j], 128, wmma::mem_row_major);
    __syncthreads();
    {
        int id = tid * 4;
#pragma unroll
        for (int rep = 0; rep < 8; rep++, id += 1024) {
            int row = id >> 7, col = id & 127;
            int gm = bm + row;
            if (gm >= NN) continue;
            float4 v = *(const float4*)&Os[row][col];
            uint2 pk;
            if (by == 0) {
                const float4 bb = *(const float4*)&b1[col];
                pk.x = pkbf(v.x + bb.x, v.y + bb.y);
                pk.y = pkbf(v.z + bb.z, v.w + bb.w);
                *(uint2*)&g_A[gm * 128 + col] = pk;
            } else {
                pk.x = pkbf(v.x, v.y);
                pk.y = pkbf(v.z, v.w);
                *(uint2*)&g_B[gm * 128 + col] = pk;
            }
        }
    }
}

__global__ void final_k(const int* __restrict__ src, const int* __restrict__ dst,
                        const float* __restrict__ w2, const float* __restrict__ b2,
                        float* __restrict__ out) {
    int e = blockIdx.x * 4 + (threadIdx.x >> 5);
    int lane = threadIdx.x & 31;
    if (e >= EE) return;
    int s = src[e], d = dst[e];
    uint2 ua = *(const uint2*)&g_A[s * 128 + lane * 4];
    uint2 ub = *(const uint2*)&g_B[d * 128 + lane * 4];
    float2 a0 = upbf(ua.x), a1 = upbf(ua.y);
    float2 b0 = upbf(ub.x), b1v = upbf(ub.y);
    float4 w = *(const float4*)&w2[lane * 4];
    float sum = fmaxf(a0.x + b0.x, 0.f) * w.x + fmaxf(a0.y + b0.y, 0.f) * w.y +
                fmaxf(a1.x + b1v.x, 0.f) * w.z + fmaxf(a1.y + b1v.y, 0.f) * w.w;
#pragma unroll
    for (int off = 16; off; off >>= 1) sum += __shfl_down_sync(0xffffffffu, sum, off);
    if (lane == 0) out[e] = 1.f / (1.f + expf(-(sum + b2[0])));
}

// ---------------- host ----------------
extern "C" void kernel_launch(void* const* d_in, const int* in_sizes, int n_in,
                              void* d_out, int out_size) {
    int b = (in_sizes[0] == 2 * EE) ? 2 : 0;
    const int* eidx = (const int*)(b ? d_in[0] : d_in[24]);
    const int* etype = (const int*)(b ? d_in[1] : d_in[25]);
    const int* src = eidx;
    const int* dst = eidx + EE;
    auto F = [&](int i) { return (const float*)d_in[i]; };

    int ptot = R0 + 4096 + 8192 + 4096;
    init_k<<<(ptot + 255) / 256, 256>>>(F(b + 0), F(b + 1), F(b + 4), F(b + 5),
                                        F(b + 8), F(b + 9), F(b + 12), F(b + 13));
    count_k<<<(EE + 255) / 256, 256>>>(etype, dst);
    scan_k<<<1, 1024>>>();
    scatter_k<<<(EE + 255) / 256, 256>>>(src, dst, etype);

    l0_agg_k<<<NN / 4, 128>>>(F(b + 2), F(b + 3));

    dim3 blk(64, 4);
    layer_k<<<NN / 4, blk>>>(F(b + 6),  F(b + 7),  1, 32, 64, 0);
    layer_k<<<NN / 4, blk>>>(F(b + 10), F(b + 11), 2, 64, 64, 1);
    layer_k<<<NN / 4, blk>>>(F(b + 14), F(b + 15), 3, 64, 32, 0);

    dim3 hg((NN + 63) / 64, 4);
    gath_gemm_k<<<hg, 256>>>(F(b + 16), F(b + 17), F(b + 18));
    gat_node_k<<<(NN + 3) / 4, 128>>>(F(b + 19));

    dim3 abgrid((NN + 63) / 64, 2);
    ab_gemm_k<<<abgrid, 256>>>(F(b + 20), F(b + 21));
    final_k<<<(EE + 3) / 4, 128>>>(src, dst, F(b + 22), F(b + 23), (float*)d_out);
}